// round 8
// baseline (speedup 1.0000x reference)
#include <cuda_runtime.h>
#include <cuda_bf16.h>
#include <cstdint>

// VectorQuantize, GB300 (sm_103 base PTX: HMMA mma.sync path).
// Pinned-exact fp32 recipe (R4, rel_err==0):
//   dot  = single fp32 accumulator, FFMA, d ascending
//   dist = __fadd_rn(__fsub_rn(xsq, __fmul_rn(2.f, dot)), csq)
//   csq  = XLA warp row-reduce; argmin = first-min
// Phase1: bf16 mma.sync filter (x converted in-kernel); gap < 0.75 -> exact rescue.

#define DDIM    256
#define KCODES  1024
#define NMAX    65536
#define RESCUE_THRESH 0.75f
#define RT      16        // tokens per rescue block-iteration

__device__ float g_csq[KCODES];
__device__ float g_cbT[DDIM * KCODES];   // [d][k] transposed codebook (exact fp32)
__device__ float g_tokloss[NMAX];
__device__ int   g_bestidx[NMAX];
__device__ int   g_rescue_list[NMAX];
__device__ int   g_rescue_cnt;
__device__ __nv_bfloat16 g_cbbf[KCODES * DDIM];

__device__ __forceinline__ uint32_t smem_u32(const void* p) {
    uint32_t a;
    asm("{ .reg .u64 t; cvta.to.shared.u64 t, %1; cvt.u32.u64 %0, t; }" : "=r"(a) : "l"(p));
    return a;
}
#define CP_ASYNC16(dst, src) \
    asm volatile("cp.async.cg.shared.global [%0], [%1], 16;" :: "r"(dst), "l"(src))
#define CP_COMMIT() asm volatile("cp.async.commit_group;" ::: "memory")
#define CP_WAIT0()  asm volatile("cp.async.wait_group 0;" ::: "memory")

__device__ __forceinline__ void ldmatrix_x4(uint32_t& r0, uint32_t& r1, uint32_t& r2,
                                            uint32_t& r3, uint32_t addr) {
    asm volatile("ldmatrix.sync.aligned.m8n8.x4.shared.b16 {%0,%1,%2,%3}, [%4];"
                 : "=r"(r0), "=r"(r1), "=r"(r2), "=r"(r3) : "r"(addr));
}
__device__ __forceinline__ void mma_bf16(float& c0, float& c1, float& c2, float& c3,
                                         uint32_t a0, uint32_t a1, uint32_t a2, uint32_t a3,
                                         uint32_t b0, uint32_t b1) {
    asm volatile("mma.sync.aligned.m16n8k16.row.col.f32.bf16.bf16.f32 "
                 "{%0,%1,%2,%3}, {%4,%5,%6,%7}, {%8,%9}, {%0,%1,%2,%3};"
                 : "+f"(c0), "+f"(c1), "+f"(c2), "+f"(c3)
                 : "r"(a0), "r"(a1), "r"(a2), "r"(a3), "r"(b0), "r"(b1));
}

// ---------------- csq + cbT + cb-bf16 + cnt reset ----------------
__global__ void csq_kernel(const float* __restrict__ cb) {
    if (blockIdx.x == 0 && threadIdx.x == 0) g_rescue_cnt = 0;
    const int warp = (blockIdx.x * blockDim.x + threadIdx.x) >> 5;
    const int lane = threadIdx.x & 31;
    if (warp >= KCODES) return;
    const float* row = cb + (size_t)warp * DDIM;
    float p = 0.f;
#pragma unroll
    for (int i = 0; i < 8; i++) {
        float v = row[lane + i * 32];
        g_cbT[(size_t)(lane + i * 32) * KCODES + warp] = v;
        g_cbbf[(size_t)warp * DDIM + lane + i * 32] = __float2bfloat16(v);
        p = __fadd_rn(p, __fmul_rn(v, v));
    }
#pragma unroll
    for (int off = 16; off > 0; off >>= 1)
        p = __fadd_rn(p, __shfl_down_sync(0xffffffffu, p, off));
    if (lane == 0) g_csq[warp] = p;
}

// ---------------- phase 1: bf16 HMMA filter ----------------
#define SA_OFF   0
#define SB_OFF   65536
#define SC_OFF   196608
#define SM_TOTAL 197632

__global__ void __launch_bounds__(256) vq_phase1(const float* __restrict__ x) {
    extern __shared__ char smem[];
    const uint32_t sb = smem_u32(smem);
    const int tid  = threadIdx.x;
    const int w    = tid >> 5;
    const int lane = tid & 31;
    const int tokenBase = blockIdx.x * 128;

    // B chunk0 + csq0 via cp.async (start them first)
    {
        const char* bsrc = reinterpret_cast<const char*>(g_cbbf);
        for (int u = tid; u < 4096; u += 256) {
            int row = u >> 5, c = u & 31;
            CP_ASYNC16(sb + SB_OFF + row * 512 + ((c ^ (row & 7)) << 4),
                       bsrc + row * 512 + (c << 4));
        }
        if (tid < 32)
            CP_ASYNC16(sb + SC_OFF + tid * 16,
                       reinterpret_cast<const char*>(g_csq) + tid * 16);
        CP_COMMIT();
    }
    // A tile: load x fp32, convert to bf16, swizzled store (values == old convert path)
    {
        const float* xsrc = x + (size_t)tokenBase * DDIM;
        for (int u = tid; u < 4096; u += 256) {
            int row = u >> 5, c = u & 31;
            const float4* p = reinterpret_cast<const float4*>(xsrc + row * DDIM + c * 8);
            float4 v0 = p[0], v1 = p[1];
            __nv_bfloat162 b0 = __floats2bfloat162_rn(v0.x, v0.y);
            __nv_bfloat162 b1 = __floats2bfloat162_rn(v0.z, v0.w);
            __nv_bfloat162 b2 = __floats2bfloat162_rn(v1.x, v1.y);
            __nv_bfloat162 b3 = __floats2bfloat162_rn(v1.z, v1.w);
            uint4 wv;
            wv.x = *reinterpret_cast<uint32_t*>(&b0);
            wv.y = *reinterpret_cast<uint32_t*>(&b1);
            wv.z = *reinterpret_cast<uint32_t*>(&b2);
            wv.w = *reinterpret_cast<uint32_t*>(&b3);
            *reinterpret_cast<uint4*>(smem + SA_OFF + row * 512 + ((c ^ (row & 7)) << 4)) = wv;
        }
    }
    CP_WAIT0();
    __syncthreads();

    const int q  = lane >> 2;
    const int qi = lane & 3;
    float bL = 3.4e38f, sL = 3.4e38f, bH = 3.4e38f, sH = 3.4e38f;
    int   iL = 0, iH = 0;

    const int arow  = w * 16 + (lane & 15);
    const uint32_t abase = sb + SA_OFF + arow * 512;
    const int asw   = arow & 7;
    const int akoff = lane >> 4;

    const int l7    = lane & 7;
    const int bnsel = lane >> 4;
    const int bkoff = (lane >> 3) & 1;
    const int bsw   = l7;

    for (int ch = 0; ch < 8; ch++) {
        const uint32_t Bcur = sb + SB_OFF + (ch & 1) * 65536;
        const float*   csqs = reinterpret_cast<const float*>(smem + SC_OFF + (ch & 1) * 512);

        if (ch + 1 < 8) {
            const uint32_t Bnxt = sb + SB_OFF + ((ch + 1) & 1) * 65536;
            const char* bsrc = reinterpret_cast<const char*>(
                g_cbbf + (size_t)(ch + 1) * 128 * DDIM);
            for (int u = tid; u < 4096; u += 256) {
                int row = u >> 5, c = u & 31;
                CP_ASYNC16(Bnxt + row * 512 + ((c ^ (row & 7)) << 4),
                           bsrc + row * 512 + (c << 4));
            }
            if (tid < 32)
                CP_ASYNC16(sb + SC_OFF + ((ch + 1) & 1) * 512 + tid * 16,
                           reinterpret_cast<const char*>(g_csq + (ch + 1) * 128) + tid * 16);
            CP_COMMIT();
        }

        float acc[16][4];
#pragma unroll
        for (int nt = 0; nt < 16; nt++)
#pragma unroll
            for (int j = 0; j < 4; j++) acc[nt][j] = 0.f;

#pragma unroll
        for (int ks = 0; ks < 16; ks++) {
            uint32_t a0, a1, a2, a3;
            ldmatrix_x4(a0, a1, a2, a3,
                        abase + (((2 * ks + akoff) ^ asw) << 4));
#pragma unroll
            for (int nt = 0; nt < 16; nt += 2) {
                uint32_t b0, b1, b2, b3;
                int brow = (nt + bnsel) * 8 + l7;
                ldmatrix_x4(b0, b1, b2, b3,
                            Bcur + brow * 512 + (((2 * ks + bkoff) ^ bsw) << 4));
                mma_bf16(acc[nt][0], acc[nt][1], acc[nt][2], acc[nt][3],
                         a0, a1, a2, a3, b0, b1);
                mma_bf16(acc[nt + 1][0], acc[nt + 1][1], acc[nt + 1][2], acc[nt + 1][3],
                         a0, a1, a2, a3, b2, b3);
            }
        }

#pragma unroll
        for (int nt = 0; nt < 16; nt++) {
            float2 cs = *reinterpret_cast<const float2*>(csqs + nt * 8 + 2 * qi);
            int code = ch * 128 + nt * 8 + 2 * qi;
            float d0 = __fmaf_rn(-2.0f, acc[nt][0], cs.x);
            float d1 = __fmaf_rn(-2.0f, acc[nt][1], cs.y);
            float d2 = __fmaf_rn(-2.0f, acc[nt][2], cs.x);
            float d3 = __fmaf_rn(-2.0f, acc[nt][3], cs.y);
            if (d0 < bL) { sL = bL; bL = d0; iL = code; } else if (d0 < sL) sL = d0;
            if (d1 < bL) { sL = bL; bL = d1; iL = code + 1; } else if (d1 < sL) sL = d1;
            if (d2 < bH) { sH = bH; bH = d2; iH = code; } else if (d2 < sH) sH = d2;
            if (d3 < bH) { sH = bH; bH = d3; iH = code + 1; } else if (d3 < sH) sH = d3;
        }

        CP_WAIT0();
        __syncthreads();
    }

#pragma unroll
    for (int m = 1; m <= 2; m <<= 1) {
        float ob = __shfl_xor_sync(0xffffffffu, bL, m);
        float os = __shfl_xor_sync(0xffffffffu, sL, m);
        int   oi = __shfl_xor_sync(0xffffffffu, iL, m);
        if (ob < bL || (ob == bL && oi < iL)) { sL = fminf(bL, os); bL = ob; iL = oi; }
        else { sL = fminf(sL, ob); }
        ob = __shfl_xor_sync(0xffffffffu, bH, m);
        os = __shfl_xor_sync(0xffffffffu, sH, m);
        oi = __shfl_xor_sync(0xffffffffu, iH, m);
        if (ob < bH || (ob == bH && oi < iH)) { sH = fminf(bH, os); bH = ob; iH = oi; }
        else { sH = fminf(sH, ob); }
    }

    if (qi == 0) {
        int tL = tokenBase + w * 16 + q;
        int tH = tL + 8;
        g_bestidx[tL] = iL;
        g_bestidx[tH] = iH;
        if (sL - bL < RESCUE_THRESH) {
            int p = atomicAdd(&g_rescue_cnt, 1);
            if (p < NMAX) g_rescue_list[p] = tL;
        }
        if (sH - bH < RESCUE_THRESH) {
            int p = atomicAdd(&g_rescue_cnt, 1);
            if (p < NMAX) g_rescue_list[p] = tH;
        }
    }
}

// ---------------- exact rescue v3: d-major x, packed-u64 reduce ----------------
// thread = 4 codes x RT tokens. Per d: 1 LDG.128 (cbT) + 4 LDS.128 (broadcast) + 64 FFMA.
#define XT_STRIDE 20
__global__ void __launch_bounds__(256) rescue_kernel(const float* __restrict__ x)
{
    __shared__ float xsT[DDIM * XT_STRIDE];           // [d][t], stride 20 floats
    __shared__ float xqv[RT];
    __shared__ int   stok[RT];
    __shared__ unsigned long long wkeys[8][RT];

    const int tid = threadIdx.x;
    const int warp = tid >> 5, lane = tid & 31;
    int cnt = g_rescue_cnt;
    if (cnt > NMAX) cnt = NMAX;

    const float4 csqv = *reinterpret_cast<const float4*>(g_csq + tid * 4);
    const float4* ct = reinterpret_cast<const float4*>(g_cbT) + tid;

    for (int base = blockIdx.x * RT; base < cnt; base += gridDim.x * RT) {
        int nt = cnt - base; if (nt > RT) nt = RT;
        __syncthreads();
        if (tid < nt) stok[tid] = g_rescue_list[base + tid];
        __syncthreads();
        for (int i = tid; i < nt * DDIM; i += 256) {
            int t = i >> 8, d = i & 255;
            xsT[d * XT_STRIDE + t] = x[(size_t)stok[t] * DDIM + d];
        }
        if (nt < RT)   // pad dead token lanes with zeros so FFMA ops are benign
            for (int i = tid; i < (RT - nt) * DDIM; i += 256) {
                int t = nt + (i >> 8), d = i & 255;
                xsT[d * XT_STRIDE + t] = 0.f;
            }
        __syncthreads();
        if (tid < nt) {   // pinned xsq: sequential d ascending, single accumulator
            float s = 0.f;
#pragma unroll 8
            for (int d = 0; d < DDIM; d++) {
                float v = xsT[d * XT_STRIDE + tid];
                s += v * v;
            }
            xqv[tid] = s;
        }
        __syncthreads();

        float a0[RT], a1[RT], a2[RT], a3[RT];
#pragma unroll
        for (int t = 0; t < RT; t++) { a0[t] = 0.f; a1[t] = 0.f; a2[t] = 0.f; a3[t] = 0.f; }

#pragma unroll 4
        for (int d = 0; d < DDIM; d++) {
            float4 c = __ldg(ct + d * (KCODES / 4));
            const float* xr = &xsT[d * XT_STRIDE];
            float4 xv0 = *reinterpret_cast<const float4*>(xr + 0);
            float4 xv1 = *reinterpret_cast<const float4*>(xr + 4);
            float4 xv2 = *reinterpret_cast<const float4*>(xr + 8);
            float4 xv3 = *reinterpret_cast<const float4*>(xr + 12);
            const float xv[RT] = { xv0.x, xv0.y, xv0.z, xv0.w,
                                   xv1.x, xv1.y, xv1.z, xv1.w,
                                   xv2.x, xv2.y, xv2.z, xv2.w,
                                   xv3.x, xv3.y, xv3.z, xv3.w };
#pragma unroll
            for (int t = 0; t < RT; t++) {
                a0[t] = __fmaf_rn(xv[t], c.x, a0[t]);
                a1[t] = __fmaf_rn(xv[t], c.y, a1[t]);
                a2[t] = __fmaf_rn(xv[t], c.z, a2[t]);
                a3[t] = __fmaf_rn(xv[t], c.w, a3[t]);
            }
        }

        // pinned dist; pack (dist_bits, code) -> u64; min = (first-min dist, lowest code)
#pragma unroll
        for (int t = 0; t < RT; t++) {
            float q = xqv[t];
            float d0 = __fadd_rn(__fsub_rn(q, __fmul_rn(2.0f, a0[t])), csqv.x);
            float d1 = __fadd_rn(__fsub_rn(q, __fmul_rn(2.0f, a1[t])), csqv.y);
            float d2 = __fadd_rn(__fsub_rn(q, __fmul_rn(2.0f, a2[t])), csqv.z);
            float d3 = __fadd_rn(__fsub_rn(q, __fmul_rn(2.0f, a3[t])), csqv.w);
            unsigned long long k0 = ((unsigned long long)__float_as_uint(d0) << 32) | (unsigned)(tid * 4);
            unsigned long long k1 = ((unsigned long long)__float_as_uint(d1) << 32) | (unsigned)(tid * 4 + 1);
            unsigned long long k2 = ((unsigned long long)__float_as_uint(d2) << 32) | (unsigned)(tid * 4 + 2);
            unsigned long long k3 = ((unsigned long long)__float_as_uint(d3) << 32) | (unsigned)(tid * 4 + 3);
            unsigned long long k = k0;
            if (k1 < k) k = k1;
            if (k2 < k) k = k2;
            if (k3 < k) k = k3;
#pragma unroll
            for (int off = 16; off > 0; off >>= 1) {
                unsigned long long o = __shfl_xor_sync(0xffffffffu, k, off);
                if (o < k) k = o;
            }
            if (lane == 0) wkeys[warp][t] = k;
        }
        __syncthreads();
        if (tid < nt) {
            unsigned long long k = wkeys[0][tid];
#pragma unroll
            for (int wv = 1; wv < 8; wv++) {
                unsigned long long o = wkeys[wv][tid];
                if (o < k) k = o;
            }
            g_bestidx[stok[tid]] = (int)(k & 0xffffffffu);
        }
    }
}

// ---------------- gather + STE + loss ----------------
__global__ void __launch_bounds__(256) gather_kernel(
    const float* __restrict__ x, const float* __restrict__ cb,
    float* __restrict__ out, float* __restrict__ oidx)
{
    const int token = (blockIdx.x * 256 + threadIdx.x) >> 5;
    const int lane = threadIdx.x & 31;
    const int k = g_bestidx[token];
    if (lane == 0 && oidx) oidx[token] = (float)k;
    const float4* xr = reinterpret_cast<const float4*>(x + (size_t)token * DDIM);
    const float4* qr = reinterpret_cast<const float4*>(cb + (size_t)k * DDIM);
    float4* orow = reinterpret_cast<float4*>(out + (size_t)token * DDIM);
    float s = 0.f;
#pragma unroll
    for (int h = 0; h < 2; h++) {
        int i = h * 32 + lane;
        float4 xv = xr[i], qv = qr[i];
        float4 o;
        o.x = xv.x + (qv.x - xv.x);
        o.y = xv.y + (qv.y - xv.y);
        o.z = xv.z + (qv.z - xv.z);
        o.w = xv.w + (qv.w - xv.w);
        orow[i] = o;
        float dx = xv.x - qv.x, dy = xv.y - qv.y, dz = xv.z - qv.z, dw = xv.w - qv.w;
        s += dx * dx + dy * dy + dz * dz + dw * dw;
    }
#pragma unroll
    for (int off = 16; off > 0; off >>= 1)
        s += __shfl_down_sync(0xffffffffu, s, off);
    if (lane == 0) g_tokloss[token] = s;
}

__global__ void loss_final(float* __restrict__ out_loss, float inv, int n) {
    __shared__ float red[1024];
    const int tid = threadIdx.x;
    float s = 0.f;
    for (int i = tid; i < n; i += 1024) s += g_tokloss[i];
    red[tid] = s;
    __syncthreads();
    for (int off = 512; off > 0; off >>= 1) {
        if (tid < off) red[tid] += red[tid + off];
        __syncthreads();
    }
    if (tid == 0) *out_loss = red[0] * inv;
}

extern "C" void kernel_launch(void* const* d_in, const int* in_sizes, int n_in,
                              void* d_out, int out_size)
{
    const float* x  = (const float*)d_in[0];
    const float* cb = (const float*)d_in[1];
    const long long n_elems = (long long)in_sizes[0];   // N * 256
    const int N = (int)(n_elems / DDIM);

    float* out   = (float*)d_out;
    float* oidx  = nullptr;
    float* oloss = nullptr;
    const long long need_idx = n_elems + N;
    if ((long long)out_size >= need_idx)      oidx  = out + n_elems;
    if ((long long)out_size >= need_idx + 1)  oloss = out + need_idx;
    else if ((long long)out_size == n_elems + 1) oloss = out + n_elems;

    cudaFuncSetAttribute(vq_phase1, cudaFuncAttributeMaxDynamicSharedMemorySize, SM_TOTAL);

    csq_kernel<<<(KCODES * 32 + 255) / 256, 256>>>(cb);
    vq_phase1<<<N / 128, 256, SM_TOTAL>>>(x);
    rescue_kernel<<<592, 256>>>(x);
    gather_kernel<<<N / 8, 256>>>(x, cb, out, oidx);
    if (oloss) loss_final<<<1, 1024>>>(oloss, 1.0f / ((float)N * (float)DDIM), N);
}

// round 9
// speedup vs baseline: 1.0750x; 1.0750x over previous
#include <cuda_runtime.h>
#include <cuda_bf16.h>
#include <cstdint>

// VectorQuantize, GB300 (sm_103 base PTX: HMMA mma.sync path).
// Pinned-exact fp32 recipe (R4, rel_err==0):
//   dot  = single fp32 accumulator, FFMA, d ascending
//   dist = __fadd_rn(__fsub_rn(xsq, __fmul_rn(2.f, dot)), csq)
//   csq  = XLA warp row-reduce; argmin = first-min
// Phase1 v3: persistent CTAs, 256 tokens/tile, B chunks of 64 codes (double-buffered),
// each warp = 32 tokens (2 m16 halves sharing B fragments). gap < 0.75 -> exact rescue.

#define DDIM    256
#define KCODES  1024
#define NMAX    65536
#define RESCUE_THRESH 0.75f
#define RT      16

__device__ float g_csq[KCODES];
__device__ float g_cbT[DDIM * KCODES];
__device__ float g_tokloss[NMAX];
__device__ int   g_bestidx[NMAX];
__device__ int   g_rescue_list[NMAX];
__device__ int   g_rescue_cnt;
__device__ int   g_tile_ctr;
__device__ __nv_bfloat16 g_cbbf[KCODES * DDIM];

__device__ __forceinline__ uint32_t smem_u32(const void* p) {
    uint32_t a;
    asm("{ .reg .u64 t; cvta.to.shared.u64 t, %1; cvt.u32.u64 %0, t; }" : "=r"(a) : "l"(p));
    return a;
}
#define CP_ASYNC16(dst, src) \
    asm volatile("cp.async.cg.shared.global [%0], [%1], 16;" :: "r"(dst), "l"(src))
#define CP_COMMIT() asm volatile("cp.async.commit_group;" ::: "memory")
#define CP_WAIT0()  asm volatile("cp.async.wait_group 0;" ::: "memory")

__device__ __forceinline__ void ldmatrix_x4(uint32_t& r0, uint32_t& r1, uint32_t& r2,
                                            uint32_t& r3, uint32_t addr) {
    asm volatile("ldmatrix.sync.aligned.m8n8.x4.shared.b16 {%0,%1,%2,%3}, [%4];"
                 : "=r"(r0), "=r"(r1), "=r"(r2), "=r"(r3) : "r"(addr));
}
__device__ __forceinline__ void mma_bf16(float& c0, float& c1, float& c2, float& c3,
                                         uint32_t a0, uint32_t a1, uint32_t a2, uint32_t a3,
                                         uint32_t b0, uint32_t b1) {
    asm volatile("mma.sync.aligned.m16n8k16.row.col.f32.bf16.bf16.f32 "
                 "{%0,%1,%2,%3}, {%4,%5,%6,%7}, {%8,%9}, {%0,%1,%2,%3};"
                 : "+f"(c0), "+f"(c1), "+f"(c2), "+f"(c3)
                 : "r"(a0), "r"(a1), "r"(a2), "r"(a3), "r"(b0), "r"(b1));
}

// ---------------- csq + cbT + cb-bf16 + counters reset ----------------
__global__ void csq_kernel(const float* __restrict__ cb) {
    if (blockIdx.x == 0 && threadIdx.x == 0) { g_rescue_cnt = 0; g_tile_ctr = 0; }
    const int warp = (blockIdx.x * blockDim.x + threadIdx.x) >> 5;
    const int lane = threadIdx.x & 31;
    if (warp >= KCODES) return;
    const float* row = cb + (size_t)warp * DDIM;
    float p = 0.f;
#pragma unroll
    for (int i = 0; i < 8; i++) {
        float v = row[lane + i * 32];
        g_cbT[(size_t)(lane + i * 32) * KCODES + warp] = v;
        g_cbbf[(size_t)warp * DDIM + lane + i * 32] = __float2bfloat16(v);
        p = __fadd_rn(p, __fmul_rn(v, v));
    }
#pragma unroll
    for (int off = 16; off > 0; off >>= 1)
        p = __fadd_rn(p, __shfl_down_sync(0xffffffffu, p, off));
    if (lane == 0) g_csq[warp] = p;
}

// ---------------- phase 1 v3 ----------------
#define PA_OFF   0                    // A: 256 rows x 512B = 131072
#define PB_OFF   131072               // B: 2 x (64 rows x 512B) = 65536
#define PC_OFF   196608               // csq: 2 x 256B
#define PTILE_OFF 197120              // tile broadcast (16B)
#define PT_TOTAL 197136

__global__ void __launch_bounds__(256, 1) vq_phase1(const float* __restrict__ x, int ntiles) {
    extern __shared__ char smem[];
    const uint32_t sb = smem_u32(smem);
    int* s_tile = reinterpret_cast<int*>(smem + PTILE_OFF);
    const int tid  = threadIdx.x;
    const int w    = tid >> 5;
    const int lane = tid & 31;

    const int q  = lane >> 2;
    const int qi = lane & 3;
    const int l7 = lane & 7;
    const int bnsel = lane >> 4;
    const int bkoff = (lane >> 3) & 1;
    const int arow  = w * 32 + (lane & 15);
    const uint32_t abase0 = sb + PA_OFF + arow * 512;
    const uint32_t abase1 = abase0 + 16 * 512;
    const int asw   = arow & 7;          // (arow+16)&7 == arow&7
    const int akoff = lane >> 4;

    for (;;) {
        if (tid == 0) s_tile[0] = atomicAdd(&g_tile_ctr, 1);
        __syncthreads();
        const int tile = s_tile[0];
        __syncthreads();
        if (tile >= ntiles) break;
        const int tokenBase = tile * 256;

        // B chunk0 (codes 0..63) + csq0
        {
            const char* bsrc = reinterpret_cast<const char*>(g_cbbf);
            for (int u = tid; u < 2048; u += 256) {
                int row = u >> 5, c = u & 31;
                CP_ASYNC16(sb + PB_OFF + row * 512 + ((c ^ (row & 7)) << 4),
                           bsrc + row * 512 + (c << 4));
            }
            if (tid < 16)
                CP_ASYNC16(sb + PC_OFF + tid * 16,
                           reinterpret_cast<const char*>(g_csq) + tid * 16);
            CP_COMMIT();
        }
        // A tile: 256 tokens, fp32 -> bf16 swizzled
        {
            const float* xsrc = x + (size_t)tokenBase * DDIM;
            for (int u = tid; u < 8192; u += 256) {
                int row = u >> 5, c = u & 31;
                const float4* p = reinterpret_cast<const float4*>(xsrc + row * DDIM + c * 8);
                float4 v0 = p[0], v1 = p[1];
                __nv_bfloat162 b0 = __floats2bfloat162_rn(v0.x, v0.y);
                __nv_bfloat162 b1 = __floats2bfloat162_rn(v0.z, v0.w);
                __nv_bfloat162 b2 = __floats2bfloat162_rn(v1.x, v1.y);
                __nv_bfloat162 b3 = __floats2bfloat162_rn(v1.z, v1.w);
                uint4 wv;
                wv.x = *reinterpret_cast<uint32_t*>(&b0);
                wv.y = *reinterpret_cast<uint32_t*>(&b1);
                wv.z = *reinterpret_cast<uint32_t*>(&b2);
                wv.w = *reinterpret_cast<uint32_t*>(&b3);
                *reinterpret_cast<uint4*>(smem + PA_OFF + row * 512 + ((c ^ (row & 7)) << 4)) = wv;
            }
        }
        CP_WAIT0();
        __syncthreads();

        // running argmin state: [half][low/high]
        float bv0 = 3.4e38f, sv0 = 3.4e38f, bv1 = 3.4e38f, sv1 = 3.4e38f;
        float bv2 = 3.4e38f, sv2 = 3.4e38f, bv3 = 3.4e38f, sv3 = 3.4e38f;
        int bi0 = 0, bi1 = 0, bi2 = 0, bi3 = 0;

        for (int ch = 0; ch < 16; ch++) {
            const uint32_t Bcur = sb + PB_OFF + (ch & 1) * 32768;
            const float*   csqs = reinterpret_cast<const float*>(smem + PC_OFF + (ch & 1) * 256);

            if (ch + 1 < 16) {
                const uint32_t Bnxt = sb + PB_OFF + ((ch + 1) & 1) * 32768;
                const char* bsrc = reinterpret_cast<const char*>(
                    g_cbbf + (size_t)(ch + 1) * 64 * DDIM);
                for (int u = tid; u < 2048; u += 256) {
                    int row = u >> 5, c = u & 31;
                    CP_ASYNC16(Bnxt + row * 512 + ((c ^ (row & 7)) << 4),
                               bsrc + row * 512 + (c << 4));
                }
                if (tid < 16)
                    CP_ASYNC16(sb + PC_OFF + ((ch + 1) & 1) * 256 + tid * 16,
                               reinterpret_cast<const char*>(g_csq + (ch + 1) * 64) + tid * 16);
                CP_COMMIT();
            }

            float acc[2][8][4];
#pragma unroll
            for (int h = 0; h < 2; h++)
#pragma unroll
                for (int nt = 0; nt < 8; nt++)
#pragma unroll
                    for (int j = 0; j < 4; j++) acc[h][nt][j] = 0.f;

#pragma unroll
            for (int ks = 0; ks < 16; ks++) {
                const uint32_t aoff = (uint32_t)(((2 * ks + akoff) ^ asw) << 4);
                uint32_t a00, a01, a02, a03, a10, a11, a12, a13;
                ldmatrix_x4(a00, a01, a02, a03, abase0 + aoff);
                ldmatrix_x4(a10, a11, a12, a13, abase1 + aoff);
#pragma unroll
                for (int ntp = 0; ntp < 4; ntp++) {
                    uint32_t b0, b1, b2, b3;
                    int brow = (ntp * 2 + bnsel) * 8 + l7;
                    ldmatrix_x4(b0, b1, b2, b3,
                                Bcur + brow * 512 + (((2 * ks + bkoff) ^ l7) << 4));
                    mma_bf16(acc[0][ntp*2][0], acc[0][ntp*2][1], acc[0][ntp*2][2], acc[0][ntp*2][3],
                             a00, a01, a02, a03, b0, b1);
                    mma_bf16(acc[0][ntp*2+1][0], acc[0][ntp*2+1][1], acc[0][ntp*2+1][2], acc[0][ntp*2+1][3],
                             a00, a01, a02, a03, b2, b3);
                    mma_bf16(acc[1][ntp*2][0], acc[1][ntp*2][1], acc[1][ntp*2][2], acc[1][ntp*2][3],
                             a10, a11, a12, a13, b0, b1);
                    mma_bf16(acc[1][ntp*2+1][0], acc[1][ntp*2+1][1], acc[1][ntp*2+1][2], acc[1][ntp*2+1][3],
                             a10, a11, a12, a13, b2, b3);
                }
            }

            // epilogue: dist = csq - 2*score; running top-2 per (half, low/high)
#pragma unroll
            for (int nt = 0; nt < 8; nt++) {
                float2 cs = *reinterpret_cast<const float2*>(csqs + nt * 8 + 2 * qi);
                int code = ch * 64 + nt * 8 + 2 * qi;
                {
                    float d0 = __fmaf_rn(-2.0f, acc[0][nt][0], cs.x);
                    float d1 = __fmaf_rn(-2.0f, acc[0][nt][1], cs.y);
                    float d2 = __fmaf_rn(-2.0f, acc[0][nt][2], cs.x);
                    float d3 = __fmaf_rn(-2.0f, acc[0][nt][3], cs.y);
                    if (d0 < bv0) { sv0 = bv0; bv0 = d0; bi0 = code; } else if (d0 < sv0) sv0 = d0;
                    if (d1 < bv0) { sv0 = bv0; bv0 = d1; bi0 = code + 1; } else if (d1 < sv0) sv0 = d1;
                    if (d2 < bv1) { sv1 = bv1; bv1 = d2; bi1 = code; } else if (d2 < sv1) sv1 = d2;
                    if (d3 < bv1) { sv1 = bv1; bv1 = d3; bi1 = code + 1; } else if (d3 < sv1) sv1 = d3;
                }
                {
                    float d0 = __fmaf_rn(-2.0f, acc[1][nt][0], cs.x);
                    float d1 = __fmaf_rn(-2.0f, acc[1][nt][1], cs.y);
                    float d2 = __fmaf_rn(-2.0f, acc[1][nt][2], cs.x);
                    float d3 = __fmaf_rn(-2.0f, acc[1][nt][3], cs.y);
                    if (d0 < bv2) { sv2 = bv2; bv2 = d0; bi2 = code; } else if (d0 < sv2) sv2 = d0;
                    if (d1 < bv2) { sv2 = bv2; bv2 = d1; bi2 = code + 1; } else if (d1 < sv2) sv2 = d1;
                    if (d2 < bv3) { sv3 = bv3; bv3 = d2; bi3 = code; } else if (d2 < sv3) sv3 = d2;
                    if (d3 < bv3) { sv3 = bv3; bv3 = d3; bi3 = code + 1; } else if (d3 < sv3) sv3 = d3;
                }
            }

            CP_WAIT0();
            __syncthreads();
        }

        // quad merge for each of the 4 states
#pragma unroll
        for (int m = 1; m <= 2; m <<= 1) {
            float ob, os; int oi;
            ob = __shfl_xor_sync(0xffffffffu, bv0, m); os = __shfl_xor_sync(0xffffffffu, sv0, m);
            oi = __shfl_xor_sync(0xffffffffu, bi0, m);
            if (ob < bv0 || (ob == bv0 && oi < bi0)) { sv0 = fminf(bv0, os); bv0 = ob; bi0 = oi; }
            else { sv0 = fminf(sv0, ob); }
            ob = __shfl_xor_sync(0xffffffffu, bv1, m); os = __shfl_xor_sync(0xffffffffu, sv1, m);
            oi = __shfl_xor_sync(0xffffffffu, bi1, m);
            if (ob < bv1 || (ob == bv1 && oi < bi1)) { sv1 = fminf(bv1, os); bv1 = ob; bi1 = oi; }
            else { sv1 = fminf(sv1, ob); }
            ob = __shfl_xor_sync(0xffffffffu, bv2, m); os = __shfl_xor_sync(0xffffffffu, sv2, m);
            oi = __shfl_xor_sync(0xffffffffu, bi2, m);
            if (ob < bv2 || (ob == bv2 && oi < bi2)) { sv2 = fminf(bv2, os); bv2 = ob; bi2 = oi; }
            else { sv2 = fminf(sv2, ob); }
            ob = __shfl_xor_sync(0xffffffffu, bv3, m); os = __shfl_xor_sync(0xffffffffu, sv3, m);
            oi = __shfl_xor_sync(0xffffffffu, bi3, m);
            if (ob < bv3 || (ob == bv3 && oi < bi3)) { sv3 = fminf(bv3, os); bv3 = ob; bi3 = oi; }
            else { sv3 = fminf(sv3, ob); }
        }

        if (qi == 0) {
            const int tb = tokenBase + w * 32;
            const int toks[4] = { tb + q, tb + q + 8, tb + 16 + q, tb + 24 + q };
            const float bvs[4] = { bv0, bv1, bv2, bv3 };
            const float svs[4] = { sv0, sv1, sv2, sv3 };
            const int   bis[4] = { bi0, bi1, bi2, bi3 };
#pragma unroll
            for (int s = 0; s < 4; s++) {
                g_bestidx[toks[s]] = bis[s];
                if (svs[s] - bvs[s] < RESCUE_THRESH) {
                    int p = atomicAdd(&g_rescue_cnt, 1);
                    if (p < NMAX) g_rescue_list[p] = toks[s];
                }
            }
        }
        __syncthreads();
    }
}

// ---------------- exact rescue v3 (unchanged from R8, passed) ----------------
#define XT_STRIDE 20
__global__ void __launch_bounds__(256) rescue_kernel(const float* __restrict__ x)
{
    __shared__ float xsT[DDIM * XT_STRIDE];
    __shared__ float xqv[RT];
    __shared__ int   stok[RT];
    __shared__ unsigned long long wkeys[8][RT];

    const int tid = threadIdx.x;
    const int warp = tid >> 5, lane = tid & 31;
    int cnt = g_rescue_cnt;
    if (cnt > NMAX) cnt = NMAX;

    const float4 csqv = *reinterpret_cast<const float4*>(g_csq + tid * 4);
    const float4* ct = reinterpret_cast<const float4*>(g_cbT) + tid;

    for (int base = blockIdx.x * RT; base < cnt; base += gridDim.x * RT) {
        int nt = cnt - base; if (nt > RT) nt = RT;
        __syncthreads();
        if (tid < nt) stok[tid] = g_rescue_list[base + tid];
        __syncthreads();
        for (int i = tid; i < nt * DDIM; i += 256) {
            int t = i >> 8, d = i & 255;
            xsT[d * XT_STRIDE + t] = x[(size_t)stok[t] * DDIM + d];
        }
        if (nt < RT)
            for (int i = tid; i < (RT - nt) * DDIM; i += 256) {
                int t = nt + (i >> 8), d = i & 255;
                xsT[d * XT_STRIDE + t] = 0.f;
            }
        __syncthreads();
        if (tid < nt) {
            float s = 0.f;
#pragma unroll 8
            for (int d = 0; d < DDIM; d++) {
                float v = xsT[d * XT_STRIDE + tid];
                s += v * v;
            }
            xqv[tid] = s;
        }
        __syncthreads();

        float a0[RT], a1[RT], a2[RT], a3[RT];
#pragma unroll
        for (int t = 0; t < RT; t++) { a0[t] = 0.f; a1[t] = 0.f; a2[t] = 0.f; a3[t] = 0.f; }

#pragma unroll 4
        for (int d = 0; d < DDIM; d++) {
            float4 c = __ldg(ct + d * (KCODES / 4));
            const float* xr = &xsT[d * XT_STRIDE];
            float4 xv0 = *reinterpret_cast<const float4*>(xr + 0);
            float4 xv1 = *reinterpret_cast<const float4*>(xr + 4);
            float4 xv2 = *reinterpret_cast<const float4*>(xr + 8);
            float4 xv3 = *reinterpret_cast<const float4*>(xr + 12);
            const float xv[RT] = { xv0.x, xv0.y, xv0.z, xv0.w,
                                   xv1.x, xv1.y, xv1.z, xv1.w,
                                   xv2.x, xv2.y, xv2.z, xv2.w,
                                   xv3.x, xv3.y, xv3.z, xv3.w };
#pragma unroll
            for (int t = 0; t < RT; t++) {
                a0[t] = __fmaf_rn(xv[t], c.x, a0[t]);
                a1[t] = __fmaf_rn(xv[t], c.y, a1[t]);
                a2[t] = __fmaf_rn(xv[t], c.z, a2[t]);
                a3[t] = __fmaf_rn(xv[t], c.w, a3[t]);
            }
        }

#pragma unroll
        for (int t = 0; t < RT; t++) {
            float q = xqv[t];
            float d0 = __fadd_rn(__fsub_rn(q, __fmul_rn(2.0f, a0[t])), csqv.x);
            float d1 = __fadd_rn(__fsub_rn(q, __fmul_rn(2.0f, a1[t])), csqv.y);
            float d2 = __fadd_rn(__fsub_rn(q, __fmul_rn(2.0f, a2[t])), csqv.z);
            float d3 = __fadd_rn(__fsub_rn(q, __fmul_rn(2.0f, a3[t])), csqv.w);
            unsigned long long k0 = ((unsigned long long)__float_as_uint(d0) << 32) | (unsigned)(tid * 4);
            unsigned long long k1 = ((unsigned long long)__float_as_uint(d1) << 32) | (unsigned)(tid * 4 + 1);
            unsigned long long k2 = ((unsigned long long)__float_as_uint(d2) << 32) | (unsigned)(tid * 4 + 2);
            unsigned long long k3 = ((unsigned long long)__float_as_uint(d3) << 32) | (unsigned)(tid * 4 + 3);
            unsigned long long k = k0;
            if (k1 < k) k = k1;
            if (k2 < k) k = k2;
            if (k3 < k) k = k3;
#pragma unroll
            for (int off = 16; off > 0; off >>= 1) {
                unsigned long long o = __shfl_xor_sync(0xffffffffu, k, off);
                if (o < k) k = o;
            }
            if (lane == 0) wkeys[warp][t] = k;
        }
        __syncthreads();
        if (tid < nt) {
            unsigned long long k = wkeys[0][tid];
#pragma unroll
            for (int wv = 1; wv < 8; wv++) {
                unsigned long long o = wkeys[wv][tid];
                if (o < k) k = o;
            }
            g_bestidx[stok[tid]] = (int)(k & 0xffffffffu);
        }
    }
}

// ---------------- gather + STE + loss ----------------
__global__ void __launch_bounds__(256) gather_kernel(
    const float* __restrict__ x, const float* __restrict__ cb,
    float* __restrict__ out, float* __restrict__ oidx)
{
    const int token = (blockIdx.x * 256 + threadIdx.x) >> 5;
    const int lane = threadIdx.x & 31;
    const int k = g_bestidx[token];
    if (lane == 0 && oidx) oidx[token] = (float)k;
    const float4* xr = reinterpret_cast<const float4*>(x + (size_t)token * DDIM);
    const float4* qr = reinterpret_cast<const float4*>(cb + (size_t)k * DDIM);
    float4* orow = reinterpret_cast<float4*>(out + (size_t)token * DDIM);
    float s = 0.f;
#pragma unroll
    for (int h = 0; h < 2; h++) {
        int i = h * 32 + lane;
        float4 xv = xr[i], qv = qr[i];
        float4 o;
        o.x = xv.x + (qv.x - xv.x);
        o.y = xv.y + (qv.y - xv.y);
        o.z = xv.z + (qv.z - xv.z);
        o.w = xv.w + (qv.w - xv.w);
        orow[i] = o;
        float dx = xv.x - qv.x, dy = xv.y - qv.y, dz = xv.z - qv.z, dw = xv.w - qv.w;
        s += dx * dx + dy * dy + dz * dz + dw * dw;
    }
#pragma unroll
    for (int off = 16; off > 0; off >>= 1)
        s += __shfl_down_sync(0xffffffffu, s, off);
    if (lane == 0) g_tokloss[token] = s;
}

__global__ void loss_final(float* __restrict__ out_loss, float inv, int n) {
    __shared__ float red[1024];
    const int tid = threadIdx.x;
    float s = 0.f;
    for (int i = tid; i < n; i += 1024) s += g_tokloss[i];
    red[tid] = s;
    __syncthreads();
    for (int off = 512; off > 0; off >>= 1) {
        if (tid < off) red[tid] += red[tid + off];
        __syncthreads();
    }
    if (tid == 0) *out_loss = red[0] * inv;
}

extern "C" void kernel_launch(void* const* d_in, const int* in_sizes, int n_in,
                              void* d_out, int out_size)
{
    const float* x  = (const float*)d_in[0];
    const float* cb = (const float*)d_in[1];
    const long long n_elems = (long long)in_sizes[0];   // N * 256
    const int N = (int)(n_elems / DDIM);
    const int ntiles = N / 256;

    float* out   = (float*)d_out;
    float* oidx  = nullptr;
    float* oloss = nullptr;
    const long long need_idx = n_elems + N;
    if ((long long)out_size >= need_idx)      oidx  = out + n_elems;
    if ((long long)out_size >= need_idx + 1)  oloss = out + need_idx;
    else if ((long long)out_size == n_elems + 1) oloss = out + n_elems;

    cudaFuncSetAttribute(vq_phase1, cudaFuncAttributeMaxDynamicSharedMemorySize, PT_TOTAL);

    csq_kernel<<<(KCODES * 32 + 255) / 256, 256>>>(cb);
    vq_phase1<<<148, 256, PT_TOTAL>>>(x, ntiles);
    rescue_kernel<<<592, 256>>>(x);
    gather_kernel<<<N / 8, 256>>>(x, cb, out, oidx);
    if (oloss) loss_final<<<1, 1024>>>(oloss, 1.0f / ((float)N * (float)DDIM), N);
}